// round 16
// baseline (speedup 1.0000x reference)
#include <cuda_runtime.h>
#include <cuda_bf16.h>
#include <math.h>
#include <stdint.h>

// ---------------- problem constants ----------------
#define Bsz     131072
#define TR      128
#define THREADS 256
#define NBLK    152
#define NTILES  (Bsz / TR)     // 1024
#define NPAIRS  (NTILES / 2)   // 512 ; pair = (pi, pi+512)
#define LN_EPS  1e-5f
#define PK      136            // bf16 pitch (elems) -> 272B rows, ldmatrix conflict-free
#define PKB     272
#define IMG_HALF   (128 * PK)            // elems in one (hi or lo) image
#define IMG_HALF_B (IMG_HALF * 2)        // 34816 bytes
#define IMG_ELEMS  (2 * 128 * PK)        // 34816 elems = 69632 B per weight image

// SMEM byte layout: two B buffers + constants + mu/rs stash
#define SM_B0   0
#define SM_B1   69632
#define SM_CB   139264                 // 6*128 floats
#define SM_CEMB (SM_CB + 3072)
#define SM_CGAM (SM_CEMB + 2048)
#define SM_CBET (SM_CGAM + 2048)
#define SM_MU   (SM_CBET + 2048)       // mu[2][4][128] floats then rs[2][4][128] floats
#define SM_TOTAL (SM_MU + 8192)

// ---------------- static device scratch ----------------
__device__ __align__(16) __nv_bfloat16 g_Bimg[12 * IMG_ELEMS];
__device__ float g_emb[512];
__device__ float g_s[(size_t)NBLK * 2 * 4 * TR * 128];   // softplus, 2 tiles per CTA

// ---------------- prep: padded bf16 hi/lo weight images + emb ----------------
__global__ void prep_kernel(const float* __restrict__ t,
                            const float* __restrict__ W_in,
                            const float* __restrict__ fw,
                            const float* __restrict__ fb,
                            const float* __restrict__ Wl,
                            const float* __restrict__ W_out) {
    int idx = blockIdx.x * blockDim.x + threadIdx.x;
    if (idx < 12 * 16384) {
        int m = idx >> 14;
        int kn = idx & 16383;
        int k = kn >> 7, n = kn & 127;   // image element B[k][n]
        float v;
        if      (m == 0)  v = W_in[n * 128 + k];                  // W_in^T
        else if (m <= 4)  v = Wl[(m - 1) * 16384 + n * 128 + k];  // Wl[i]^T
        else if (m == 5)  v = W_out[n * 128 + k];                 // W_out^T
        else if (m == 6)  v = W_out[k * 128 + n];                 // W_out
        else if (m <= 10) v = Wl[(m - 7) * 16384 + k * 128 + n];  // Wl[i]
        else              v = W_in[k * 128 + n];                  // W_in
        __nv_bfloat16 h = __float2bfloat16(v);
        __nv_bfloat16 l = __float2bfloat16(v - __bfloat162float(h));
        g_Bimg[m * IMG_ELEMS + k * PK + n] = h;
        g_Bimg[m * IMG_ELEMS + IMG_HALF + k * PK + n] = l;
    } else if (idx < 12 * 16384 + 512) {
        int j = idx - 12 * 16384;
        g_emb[j] = sinf(t[0] * fw[j] + fb[j]);
    }
}

// ---------------- PTX helpers ----------------
__device__ __forceinline__ uint32_t smem_u32(const void* p) {
    uint32_t a;
    asm("{ .reg .u64 t; cvta.to.shared.u64 t, %1; cvt.u32.u64 %0, t; }" : "=r"(a) : "l"(p));
    return a;
}
__device__ __forceinline__ void ldsm4t(uint32_t r[4], uint32_t addr) {
    asm volatile("ldmatrix.sync.aligned.m8n8.x4.trans.shared.b16 {%0,%1,%2,%3}, [%4];"
                 : "=r"(r[0]), "=r"(r[1]), "=r"(r[2]), "=r"(r[3]) : "r"(addr));
}
__device__ __forceinline__ void mma16816(float c[4], const uint32_t a[4],
                                         uint32_t b0, uint32_t b1) {
    asm volatile("mma.sync.aligned.m16n8k16.row.col.f32.bf16.bf16.f32 "
                 "{%0,%1,%2,%3},{%4,%5,%6,%7},{%8,%9},{%0,%1,%2,%3};"
                 : "+f"(c[0]), "+f"(c[1]), "+f"(c[2]), "+f"(c[3])
                 : "r"(a[0]), "r"(a[1]), "r"(a[2]), "r"(a[3]), "r"(b0), "r"(b1));
}
// pack {x,y} -> bf16x2 hi + residual bf16x2 lo
__device__ __forceinline__ void pack2(float x, float y, uint32_t& hi, uint32_t& lo) {
    asm("cvt.rn.bf16x2.f32 %0, %1, %2;" : "=r"(hi) : "f"(y), "f"(x));
    float hx = __uint_as_float(hi << 16);
    float hy = __uint_as_float(hi & 0xffff0000u);
    asm("cvt.rn.bf16x2.f32 %0, %1, %2;" : "=r"(lo) : "f"(y - hy), "f"(x - hx));
}
__device__ __forceinline__ float qreduce(float v) {   // sum over quad (lanes xor 1,2)
    v += __shfl_xor_sync(0xffffffffu, v, 1);
    v += __shfl_xor_sync(0xffffffffu, v, 2);
    return v;
}
__device__ __forceinline__ float softplusf_(float u) {
    return fmaxf(u, 0.f) + __logf(1.f + __expf(-fabsf(u)));
}
__device__ __forceinline__ int mat_for(int g) {
    return (g <= 6) ? g : (g == 11 ? 11 : 17 - g);
}

// async 69632B copy global -> smem (all 256 threads), one commit group
__device__ __forceinline__ void copyB_async(uint32_t dst, const __nv_bfloat16* src, int tid) {
    const char* s = (const char*)src + tid * 16;
    uint32_t d = dst + tid * 16;
#pragma unroll
    for (int it = 0; it < 17; it++)
        asm volatile("cp.async.cg.shared.global [%0], [%1], 16;"
                     :: "r"(d + it * 4096), "l"(s + it * 4096));
    asm volatile("cp.async.commit_group;" ::: "memory");
}

// ---------------- per-warp stage subroutines ----------------
__device__ __forceinline__ void pack_all(const float (&acc)[16][4],
                                         uint32_t (&aH)[8][4], uint32_t (&aL)[8][4]) {
#pragma unroll
    for (int ks = 0; ks < 8; ks++) {
        pack2(acc[2*ks][0],   acc[2*ks][1],   aH[ks][0], aL[ks][0]);
        pack2(acc[2*ks][2],   acc[2*ks][3],   aH[ks][1], aL[ks][1]);
        pack2(acc[2*ks+1][0], acc[2*ks+1][1], aH[ks][2], aL[ks][2]);
        pack2(acc[2*ks+1][2], acc[2*ks+1][3], aH[ks][3], aL[ks][3]);
    }
}

// acc = (Ah*Bh + Al*Bh + Ah*Bl) for one 128x128x128 GEMM
__device__ __forceinline__ void gemm_step(float (&acc)[16][4],
                                          const uint32_t (&aH)[8][4],
                                          const uint32_t (&aL)[8][4],
                                          uint32_t bbase) {
#pragma unroll
    for (int nt = 0; nt < 16; nt++)
#pragma unroll
        for (int q = 0; q < 4; q++) acc[nt][q] = 0.f;
#pragma unroll
    for (int ks = 0; ks < 8; ks++) {
        const uint32_t krow = bbase + (uint32_t)(ks * 16) * PKB;
#pragma unroll
        for (int nt = 0; nt < 16; nt++) {
            uint32_t bf[4];                  // bh0,bh1,bl0,bl1
            ldsm4t(bf, krow + nt * 16);
            mma16816(acc[nt], aH[ks], bf[0], bf[1]);
            mma16816(acc[nt], aL[ks], bf[0], bf[1]);
            mma16816(acc[nt], aH[ks], bf[2], bf[3]);
        }
    }
}

// epilogue for stages 0..10 on one tile (acc -> input of next stage)
__device__ __forceinline__ void epi_mid(
    int ge, float (&acc)[16][4], int ts /*tile sel 0/1*/,
    const float* cb, const float* cemb, const float* cgam, const float* cbet,
    float* pmu,
    const float* __restrict__ w, float* __restrict__ out,
    float* g_s_t, size_t row0, int colb, int rwA, int rwB, int qc) {
    if (ge <= 4) {                      // + bias (b_in, bl0..3)
        const float* bp = cb + ge * 128 + colb;
#pragma unroll
        for (int nt = 0; nt < 16; nt++) {
            float2 b2 = *(const float2*)(bp + nt * 8);
            acc[nt][0] += b2.x; acc[nt][1] += b2.y;
            acc[nt][2] += b2.x; acc[nt][3] += b2.y;
        }
    }
    if (ge <= 3) {                      // fwd layer ge: emb, softplus, LN
        const float* eb = cemb + ge * 128 + colb;
        const float* ga = cgam + ge * 128 + colb;
        const float* be = cbet + ge * 128 + colb;
#pragma unroll
        for (int rb = 0; rb < 2; rb++) {
            int rw = rb ? rwB : rwA;
            float sum = 0.f;
#pragma unroll
            for (int nt = 0; nt < 16; nt++) {
                float2 e2 = *(const float2*)(eb + nt * 8);
                float s0 = softplusf_(acc[nt][2*rb]   + e2.x);
                float s1 = softplusf_(acc[nt][2*rb+1] + e2.y);
                acc[nt][2*rb] = s0; acc[nt][2*rb+1] = s1;
                sum += s0 + s1;
            }
            float mu = qreduce(sum) * (1.f / 128.f);
            float ssq = 0.f;
#pragma unroll
            for (int nt = 0; nt < 16; nt++) {
                float d0 = acc[nt][2*rb] - mu, d1 = acc[nt][2*rb+1] - mu;
                ssq += d0 * d0 + d1 * d1;
            }
            float rs = rsqrtf(qreduce(ssq) * (1.f / 128.f) + LN_EPS);
            if (qc == 0) {
                int mi = (ts * 4 + ge) * 128 + rw;
                pmu[mi] = mu; pmu[1024 + mi] = rs;
            }
            float* sp = g_s_t + ((size_t)ge * 128 + rw) * 128 + colb;
#pragma unroll
            for (int nt = 0; nt < 16; nt++)
                *(float2*)(sp + nt * 8) =
                    make_float2(acc[nt][2*rb], acc[nt][2*rb+1]);
#pragma unroll
            for (int nt = 0; nt < 16; nt++) {
                float2 g2 = *(const float2*)(ga + nt * 8);
                float2 t2 = *(const float2*)(be + nt * 8);
                acc[nt][2*rb]   = (acc[nt][2*rb]   - mu) * rs * g2.x + t2.x;
                acc[nt][2*rb+1] = (acc[nt][2*rb+1] - mu) * rs * g2.y + t2.y;
            }
        }
    } else if (ge == 5) {               // dp out (+b_out); load w rows into acc
        const float* bp = cb + 640 + colb;
#pragma unroll
        for (int rb = 0; rb < 2; rb++) {
            int rw = rb ? rwB : rwA;
            float* dst = out + (row0 + rw) * 128 + colb;
#pragma unroll
            for (int nt = 0; nt < 16; nt++) {
                float2 b2 = *(const float2*)(bp + nt * 8);
                *(float2*)(dst + nt * 8) =
                    make_float2(acc[nt][2*rb] + b2.x, acc[nt][2*rb+1] + b2.y);
            }
            const float* src = w + (row0 + rw) * 128 + colb;
#pragma unroll
            for (int nt = 0; nt < 16; nt++) {
                float2 v = *(const float2*)(src + nt * 8);
                acc[nt][2*rb] = v.x; acc[nt][2*rb+1] = v.y;
            }
        }
    } else if (ge >= 7) {               // bwd layer l = 10-ge
        int l = 10 - ge;
        const float* ga = cgam + l * 128 + colb;
#pragma unroll
        for (int rb = 0; rb < 2; rb++) {
            int rw = rb ? rwB : rwA;
            int mi = (ts * 4 + l) * 128 + rw;
            float mu = pmu[mi], rs = pmu[1024 + mi];
            const float* sp = g_s_t + ((size_t)l * 128 + rw) * 128 + colb;
            float sv[32];
#pragma unroll
            for (int nt = 0; nt < 16; nt++) {
                float2 s2 = *(const float2*)(sp + nt * 8);
                sv[2*nt] = s2.x; sv[2*nt+1] = s2.y;
            }
            float m1 = 0.f, m2 = 0.f;
#pragma unroll
            for (int nt = 0; nt < 16; nt++) {
                float2 g2 = *(const float2*)(ga + nt * 8);
                float t0 = acc[nt][2*rb]   * g2.x;
                float t1 = acc[nt][2*rb+1] * g2.y;
                m1 += t0 + t1;
                m2 += t0 * ((sv[2*nt]   - mu) * rs) +
                      t1 * ((sv[2*nt+1] - mu) * rs);
            }
            m1 = qreduce(m1) * (1.f / 128.f);
            m2 = qreduce(m2) * (1.f / 128.f);
#pragma unroll
            for (int nt = 0; nt < 16; nt++) {
                float2 g2 = *(const float2*)(ga + nt * 8);
                float t0 = acc[nt][2*rb]   * g2.x;
                float t1 = acc[nt][2*rb+1] * g2.y;
                float x0 = (sv[2*nt]   - mu) * rs;
                float x1 = (sv[2*nt+1] - mu) * rs;
                acc[nt][2*rb]   = rs * (t0 - m1 - x0 * m2) * (1.f - __expf(-sv[2*nt]));
                acc[nt][2*rb+1] = rs * (t1 - m1 - x1 * m2) * (1.f - __expf(-sv[2*nt+1]));
            }
        }
    }
    // ge == 4 (bias only) and ge == 6: nothing further
}

__device__ __forceinline__ void load_p_acc(float (&acc)[16][4],
                                           const float* __restrict__ p,
                                           size_t row0, int colb, int rwA, int rwB) {
    const float* pA = p + (row0 + rwA) * 128 + colb;
    const float* pB = p + (row0 + rwB) * 128 + colb;
#pragma unroll
    for (int nt = 0; nt < 16; nt++) {
        float2 va = *(const float2*)(pA + nt * 8);
        float2 vb = *(const float2*)(pB + nt * 8);
        acc[nt][0] = va.x; acc[nt][1] = va.y;
        acc[nt][2] = vb.x; acc[nt][3] = vb.y;
    }
}

__device__ __forceinline__ void store_dw(const float (&acc)[16][4],
                                         float* __restrict__ dwo,
                                         size_t row0, int colb, int rwA, int rwB) {
#pragma unroll
    for (int rb = 0; rb < 2; rb++) {
        int rw = rb ? rwB : rwA;
        float* dst = dwo + (row0 + rw) * 128 + colb;
#pragma unroll
        for (int nt = 0; nt < 16; nt++)
            *(float2*)(dst + nt * 8) =
                make_float2(-acc[nt][2*rb], -acc[nt][2*rb+1]);
    }
}

// ---------------- main kernel ----------------
extern __shared__ __align__(16) char smem[];

__global__ void __launch_bounds__(THREADS)
clnf_main(const float* __restrict__ p, const float* __restrict__ w,
          const float* __restrict__ b_in, const float* __restrict__ gamma,
          const float* __restrict__ beta, const float* __restrict__ bl,
          const float* __restrict__ b_out, float* __restrict__ out) {
    const int tid  = threadIdx.x;
    const int warp = tid >> 5, lane = tid & 31;
    const int qr   = lane >> 2, qc = lane & 3;
    const int rwA  = warp * 16 + qr;
    const int rwB  = rwA + 8;
    const int colb = qc * 2;

    const uint32_t sbase = smem_u32(smem);
    float* cb   = (float*)(smem + SM_CB);
    float* cemb = (float*)(smem + SM_CEMB);
    float* cgam = (float*)(smem + SM_CGAM);
    float* cbet = (float*)(smem + SM_CBET);
    float* pmu  = (float*)(smem + SM_MU);
    float* dwo  = out + (size_t)Bsz * 128;
    float* g_s1 = g_s + (size_t)blockIdx.x * (2 * 4 * TR * 128);
    float* g_s2 = g_s1 + 4 * TR * 128;

    // consts -> SMEM
    if (tid < 128) { cb[tid] = b_in[tid]; cb[640 + tid] = b_out[tid]; }
#pragma unroll
    for (int i = 0; i < 2; i++) {
        int j = tid + i * 256;
        cb[128 + j] = bl[j];
        cemb[j] = g_emb[j];
        cgam[j] = gamma[j];
        cbet[j] = beta[j];
    }
    // preload B image 0 into buf0
    copyB_async(sbase + SM_B0, g_Bimg, tid);
    asm volatile("cp.async.wait_group 0;" ::: "memory");
    __syncthreads();

    const uint32_t lane_b = (uint32_t)(lane & 15) * PKB + (uint32_t)(lane >> 4) * IMG_HALF_B;

    float acc1[16][4], acc2[16][4];
    uint32_t aH[8][4], aL[8][4];

    for (int pi = blockIdx.x; pi < NPAIRS; pi += NBLK) {
        const size_t row1 = (size_t)pi * TR;
        const size_t row2 = (size_t)(pi + NPAIRS) * TR;

        load_p_acc(acc1, p, row1, colb, rwA, rwB);
        load_p_acc(acc2, p, row2, colb, rwA, rwB);

        for (int g = 0; g < 12; g++) {
            // prefetch next weight image into the other buffer
            {
                int gn = (g == 11) ? 0 : g + 1;
                copyB_async(sbase + ((g & 1) ? SM_B0 : SM_B1),
                            g_Bimg + (size_t)mat_for(gn) * IMG_ELEMS, tid);
            }
            const uint32_t bbase = sbase + ((g & 1) ? SM_B1 : SM_B0) + lane_b;

            // tile1 GEMM
            pack_all(acc1, aH, aL);
            gemm_step(acc1, aH, aL, bbase);
            // tile2 GEMM (A-frag regs reused after tile1 MMAs issued)
            pack_all(acc2, aH, aL);
            gemm_step(acc2, aH, aL, bbase);

            // epilogues: epi1 issues while tile2 MMAs drain
            if (g < 11) {
                epi_mid(g, acc1, 0, cb, cemb, cgam, cbet, pmu,
                        w, out, g_s1, row1, colb, rwA, rwB, qc);
                epi_mid(g, acc2, 1, cb, cemb, cgam, cbet, pmu,
                        w, out, g_s2, row2, colb, rwA, rwB, qc);
            } else {
                store_dw(acc1, dwo, row1, colb, rwA, rwB);
                store_dw(acc2, dwo, row2, colb, rwA, rwB);
            }

            asm volatile("cp.async.wait_group 0;" ::: "memory");
            __syncthreads();   // B double-buffer handoff
        }
    }
}

// ---------------- launch ----------------
extern "C" void kernel_launch(void* const* d_in, const int* in_sizes, int n_in,
                              void* d_out, int out_size) {
    const float* t     = (const float*)d_in[0];
    const float* p     = (const float*)d_in[1];
    const float* w     = (const float*)d_in[2];
    const float* W_in  = (const float*)d_in[3];
    const float* b_in  = (const float*)d_in[4];
    const float* fw    = (const float*)d_in[5];
    const float* fb    = (const float*)d_in[6];
    const float* gamma = (const float*)d_in[7];
    const float* beta  = (const float*)d_in[8];
    const float* Wl    = (const float*)d_in[9];
    const float* bl    = (const float*)d_in[10];
    const float* W_out = (const float*)d_in[11];
    const float* b_out = (const float*)d_in[12];
    float* out = (float*)d_out;

    cudaFuncSetAttribute(clnf_main, cudaFuncAttributeMaxDynamicSharedMemorySize,
                         SM_TOTAL);

    int prep_total = 12 * 16384 + 512;
    prep_kernel<<<(prep_total + 255) / 256, 256>>>(t, W_in, fw, fb, Wl, W_out);
    clnf_main<<<NBLK, THREADS, SM_TOTAL>>>(p, w, b_in, gamma, beta, bl, b_out, out);
}

// round 17
// speedup vs baseline: 1.3614x; 1.3614x over previous
#include <cuda_runtime.h>
#include <cuda_bf16.h>
#include <math.h>
#include <stdint.h>

// ---------------- problem constants ----------------
#define Bsz     131072
#define TR      64             // rows per tile (64 rows -> 4 warps)
#define THREADS 128
#define NBLK    304            // 2 CTAs per SM
#define NTILES  (Bsz / TR)     // 2048
#define LN_EPS  1e-5f
#define PK      136            // bf16 pitch (elems) -> 272B rows, ldmatrix conflict-free
#define PKB     272
#define IMG_HALF   (128 * PK)            // elems in one (hi or lo) image
#define IMG_HALF_B (IMG_HALF * 2)        // 34816 bytes
#define IMG_ELEMS  (2 * 128 * PK)        // 34816 elems = 69632 B per weight image

// SMEM byte layout: ONE B buffer + constants (fits 2 CTAs/SM)
#define SM_B0   0
#define SM_CB   69632                  // 6*128 floats
#define SM_CEMB (SM_CB + 3072)
#define SM_CGAM (SM_CEMB + 2048)
#define SM_CBET (SM_CGAM + 2048)
#define SM_TOTAL (SM_CBET + 2048)      // 78848 B per CTA

// ---------------- static device scratch ----------------
__device__ __align__(16) __nv_bfloat16 g_Bimg[12 * IMG_ELEMS];
__device__ float g_emb[512];
__device__ float g_s[(size_t)NBLK * 4 * TR * 128];   // saved softplus per CTA

// ---------------- prep: padded bf16 hi/lo weight images + emb ----------------
__global__ void prep_kernel(const float* __restrict__ t,
                            const float* __restrict__ W_in,
                            const float* __restrict__ fw,
                            const float* __restrict__ fb,
                            const float* __restrict__ Wl,
                            const float* __restrict__ W_out) {
    int idx = blockIdx.x * blockDim.x + threadIdx.x;
    if (idx < 12 * 16384) {
        int m = idx >> 14;
        int kn = idx & 16383;
        int k = kn >> 7, n = kn & 127;   // image element B[k][n]
        float v;
        if      (m == 0)  v = W_in[n * 128 + k];                  // W_in^T
        else if (m <= 4)  v = Wl[(m - 1) * 16384 + n * 128 + k];  // Wl[i]^T
        else if (m == 5)  v = W_out[n * 128 + k];                 // W_out^T
        else if (m == 6)  v = W_out[k * 128 + n];                 // W_out
        else if (m <= 10) v = Wl[(m - 7) * 16384 + k * 128 + n];  // Wl[i]
        else              v = W_in[k * 128 + n];                  // W_in
        __nv_bfloat16 h = __float2bfloat16(v);
        __nv_bfloat16 l = __float2bfloat16(v - __bfloat162float(h));
        g_Bimg[m * IMG_ELEMS + k * PK + n] = h;
        g_Bimg[m * IMG_ELEMS + IMG_HALF + k * PK + n] = l;
    } else if (idx < 12 * 16384 + 512) {
        int j = idx - 12 * 16384;
        g_emb[j] = sinf(t[0] * fw[j] + fb[j]);
    }
}

// ---------------- PTX helpers ----------------
__device__ __forceinline__ uint32_t smem_u32(const void* p) {
    uint32_t a;
    asm("{ .reg .u64 t; cvta.to.shared.u64 t, %1; cvt.u32.u64 %0, t; }" : "=r"(a) : "l"(p));
    return a;
}
__device__ __forceinline__ void ldsm4t(uint32_t r[4], uint32_t addr) {
    asm volatile("ldmatrix.sync.aligned.m8n8.x4.trans.shared.b16 {%0,%1,%2,%3}, [%4];"
                 : "=r"(r[0]), "=r"(r[1]), "=r"(r[2]), "=r"(r[3]) : "r"(addr));
}
__device__ __forceinline__ void mma16816(float c[4], const uint32_t a[4],
                                         uint32_t b0, uint32_t b1) {
    asm volatile("mma.sync.aligned.m16n8k16.row.col.f32.bf16.bf16.f32 "
                 "{%0,%1,%2,%3},{%4,%5,%6,%7},{%8,%9},{%0,%1,%2,%3};"
                 : "+f"(c[0]), "+f"(c[1]), "+f"(c[2]), "+f"(c[3])
                 : "r"(a[0]), "r"(a[1]), "r"(a[2]), "r"(a[3]), "r"(b0), "r"(b1));
}
// pack {x,y} -> bf16x2 hi + residual bf16x2 lo
__device__ __forceinline__ void pack2(float x, float y, uint32_t& hi, uint32_t& lo) {
    asm("cvt.rn.bf16x2.f32 %0, %1, %2;" : "=r"(hi) : "f"(y), "f"(x));
    float hx = __uint_as_float(hi << 16);
    float hy = __uint_as_float(hi & 0xffff0000u);
    asm("cvt.rn.bf16x2.f32 %0, %1, %2;" : "=r"(lo) : "f"(y - hy), "f"(x - hx));
}
__device__ __forceinline__ float qreduce(float v) {   // sum over quad (lanes xor 1,2)
    v += __shfl_xor_sync(0xffffffffu, v, 1);
    v += __shfl_xor_sync(0xffffffffu, v, 2);
    return v;
}
__device__ __forceinline__ float softplusf_(float u) {
    return fmaxf(u, 0.f) + __logf(1.f + __expf(-fabsf(u)));
}
__device__ __forceinline__ int mat_for(int g) {
    return (g <= 6) ? g : (g == 11 ? 11 : 17 - g);
}

// async 69632B copy global -> smem (all 128 threads), one commit group
__device__ __forceinline__ void copyB_async(uint32_t dst, const __nv_bfloat16* src, int tid) {
    const char* s = (const char*)src + tid * 16;
    uint32_t d = dst + tid * 16;
#pragma unroll
    for (int it = 0; it < 34; it++)
        asm volatile("cp.async.cg.shared.global [%0], [%1], 16;"
                     :: "r"(d + it * 2048), "l"(s + it * 2048));
    asm volatile("cp.async.commit_group;" ::: "memory");
}

// ---------------- per-warp stage subroutines ----------------
__device__ __forceinline__ void pack_all(const float (&acc)[16][4],
                                         uint32_t (&aH)[8][4], uint32_t (&aL)[8][4]) {
#pragma unroll
    for (int ks = 0; ks < 8; ks++) {
        pack2(acc[2*ks][0],   acc[2*ks][1],   aH[ks][0], aL[ks][0]);
        pack2(acc[2*ks][2],   acc[2*ks][3],   aH[ks][1], aL[ks][1]);
        pack2(acc[2*ks+1][0], acc[2*ks+1][1], aH[ks][2], aL[ks][2]);
        pack2(acc[2*ks+1][2], acc[2*ks+1][3], aH[ks][3], aL[ks][3]);
    }
}

// acc = (Ah*Bh + Al*Bh + Ah*Bl) for one 64x128x128 warp-slice GEMM
__device__ __forceinline__ void gemm_step(float (&acc)[16][4],
                                          const uint32_t (&aH)[8][4],
                                          const uint32_t (&aL)[8][4],
                                          uint32_t bbase) {
#pragma unroll
    for (int nt = 0; nt < 16; nt++)
#pragma unroll
        for (int q = 0; q < 4; q++) acc[nt][q] = 0.f;
#pragma unroll
    for (int ks = 0; ks < 8; ks++) {
        const uint32_t krow = bbase + (uint32_t)(ks * 16) * PKB;
#pragma unroll
        for (int nt = 0; nt < 16; nt++) {
            uint32_t bf[4];                  // bh0,bh1,bl0,bl1
            ldsm4t(bf, krow + nt * 16);
            mma16816(acc[nt], aH[ks], bf[0], bf[1]);
            mma16816(acc[nt], aL[ks], bf[0], bf[1]);
            mma16816(acc[nt], aH[ks], bf[2], bf[3]);
        }
    }
}

// epilogue for stages 0..10 (acc -> input of next stage)
__device__ __forceinline__ void epi_mid(
    int ge, float (&acc)[16][4], float (&mus)[4][2], float (&rss)[4][2],
    const float* cb, const float* cemb, const float* cgam, const float* cbet,
    const float* __restrict__ w, float* __restrict__ out,
    float* g_s_cta, size_t row0, int colb, int rwA, int rwB) {
    if (ge <= 4) {                      // + bias (b_in, bl0..3)
        const float* bp = cb + ge * 128 + colb;
#pragma unroll
        for (int nt = 0; nt < 16; nt++) {
            float2 b2 = *(const float2*)(bp + nt * 8);
            acc[nt][0] += b2.x; acc[nt][1] += b2.y;
            acc[nt][2] += b2.x; acc[nt][3] += b2.y;
        }
    }
    if (ge <= 3) {                      // fwd layer ge: emb, softplus, LN
        const float* eb = cemb + ge * 128 + colb;
        const float* ga = cgam + ge * 128 + colb;
        const float* be = cbet + ge * 128 + colb;
#pragma unroll
        for (int rb = 0; rb < 2; rb++) {
            int rw = rb ? rwB : rwA;
            float sum = 0.f;
#pragma unroll
            for (int nt = 0; nt < 16; nt++) {
                float2 e2 = *(const float2*)(eb + nt * 8);
                float s0 = softplusf_(acc[nt][2*rb]   + e2.x);
                float s1 = softplusf_(acc[nt][2*rb+1] + e2.y);
                acc[nt][2*rb] = s0; acc[nt][2*rb+1] = s1;
                sum += s0 + s1;
            }
            float mu = qreduce(sum) * (1.f / 128.f);
            float ssq = 0.f;
#pragma unroll
            for (int nt = 0; nt < 16; nt++) {
                float d0 = acc[nt][2*rb] - mu, d1 = acc[nt][2*rb+1] - mu;
                ssq += d0 * d0 + d1 * d1;
            }
            float rs = rsqrtf(qreduce(ssq) * (1.f / 128.f) + LN_EPS);
            mus[ge][rb] = mu; rss[ge][rb] = rs;
            float* sp = g_s_cta + ((size_t)ge * TR + rw) * 128 + colb;
#pragma unroll
            for (int nt = 0; nt < 16; nt++)
                *(float2*)(sp + nt * 8) =
                    make_float2(acc[nt][2*rb], acc[nt][2*rb+1]);
#pragma unroll
            for (int nt = 0; nt < 16; nt++) {
                float2 g2 = *(const float2*)(ga + nt * 8);
                float2 t2 = *(const float2*)(be + nt * 8);
                acc[nt][2*rb]   = (acc[nt][2*rb]   - mu) * rs * g2.x + t2.x;
                acc[nt][2*rb+1] = (acc[nt][2*rb+1] - mu) * rs * g2.y + t2.y;
            }
        }
    } else if (ge == 5) {               // dp out (+b_out); load w rows into acc
        const float* bp = cb + 640 + colb;
#pragma unroll
        for (int rb = 0; rb < 2; rb++) {
            int rw = rb ? rwB : rwA;
            float* dst = out + (row0 + rw) * 128 + colb;
#pragma unroll
            for (int nt = 0; nt < 16; nt++) {
                float2 b2 = *(const float2*)(bp + nt * 8);
                *(float2*)(dst + nt * 8) =
                    make_float2(acc[nt][2*rb] + b2.x, acc[nt][2*rb+1] + b2.y);
            }
            const float* src = w + (row0 + rw) * 128 + colb;
#pragma unroll
            for (int nt = 0; nt < 16; nt++) {
                float2 v = *(const float2*)(src + nt * 8);
                acc[nt][2*rb] = v.x; acc[nt][2*rb+1] = v.y;
            }
        }
    } else if (ge >= 7) {               // bwd layer l = 10-ge
        int l = 10 - ge;
        const float* ga = cgam + l * 128 + colb;
#pragma unroll
        for (int rb = 0; rb < 2; rb++) {
            int rw = rb ? rwB : rwA;
            float mu = mus[l][rb], rs = rss[l][rb];
            const float* sp = g_s_cta + ((size_t)l * TR + rw) * 128 + colb;
            float sv[32];
#pragma unroll
            for (int nt = 0; nt < 16; nt++) {
                float2 s2 = *(const float2*)(sp + nt * 8);
                sv[2*nt] = s2.x; sv[2*nt+1] = s2.y;
            }
            float m1 = 0.f, m2 = 0.f;
#pragma unroll
            for (int nt = 0; nt < 16; nt++) {
                float2 g2 = *(const float2*)(ga + nt * 8);
                float t0 = acc[nt][2*rb]   * g2.x;
                float t1 = acc[nt][2*rb+1] * g2.y;
                m1 += t0 + t1;
                m2 += t0 * ((sv[2*nt]   - mu) * rs) +
                      t1 * ((sv[2*nt+1] - mu) * rs);
            }
            m1 = qreduce(m1) * (1.f / 128.f);
            m2 = qreduce(m2) * (1.f / 128.f);
#pragma unroll
            for (int nt = 0; nt < 16; nt++) {
                float2 g2 = *(const float2*)(ga + nt * 8);
                float t0 = acc[nt][2*rb]   * g2.x;
                float t1 = acc[nt][2*rb+1] * g2.y;
                float x0 = (sv[2*nt]   - mu) * rs;
                float x1 = (sv[2*nt+1] - mu) * rs;
                acc[nt][2*rb]   = rs * (t0 - m1 - x0 * m2) * (1.f - __expf(-sv[2*nt]));
                acc[nt][2*rb+1] = rs * (t1 - m1 - x1 * m2) * (1.f - __expf(-sv[2*nt+1]));
            }
        }
    }
    // ge == 4 (bias only) and ge == 6: nothing further
}

// ---------------- main kernel ----------------
extern __shared__ __align__(16) char smem[];

__global__ void __launch_bounds__(THREADS)
clnf_main(const float* __restrict__ p, const float* __restrict__ w,
          const float* __restrict__ b_in, const float* __restrict__ gamma,
          const float* __restrict__ beta, const float* __restrict__ bl,
          const float* __restrict__ b_out, float* __restrict__ out) {
    const int tid  = threadIdx.x;
    const int warp = tid >> 5, lane = tid & 31;
    const int qr   = lane >> 2, qc = lane & 3;
    const int rwA  = warp * 16 + qr;          // rows 0..63
    const int rwB  = rwA + 8;
    const int colb = qc * 2;

    const uint32_t sbase = smem_u32(smem);
    float* cb   = (float*)(smem + SM_CB);
    float* cemb = (float*)(smem + SM_CEMB);
    float* cgam = (float*)(smem + SM_CGAM);
    float* cbet = (float*)(smem + SM_CBET);
    float* dwo  = out + (size_t)Bsz * 128;
    float* g_s_cta = g_s + (size_t)blockIdx.x * (4 * TR * 128);

    // consts -> SMEM (128 threads)
    cb[tid] = b_in[tid];
    cb[640 + tid] = b_out[tid];
#pragma unroll
    for (int i = 0; i < 4; i++) {
        int j = tid + i * 128;
        cb[128 + j] = bl[j];
        cemb[j] = g_emb[j];
        cgam[j] = gamma[j];
        cbet[j] = beta[j];
    }
    // preload B image 0
    copyB_async(sbase + SM_B0, g_Bimg, tid);
    asm volatile("cp.async.wait_group 0;" ::: "memory");
    __syncthreads();

    // per-lane B base: lanes 0-15 -> hi image rows, lanes 16-31 -> lo image rows
    const uint32_t bbase = sbase + SM_B0 +
        (uint32_t)(lane & 15) * PKB + (uint32_t)(lane >> 4) * IMG_HALF_B;

    float mus[4][2], rss[4][2];
    float acc[16][4];
    uint32_t aH[8][4], aL[8][4];

    for (int tile = blockIdx.x; tile < NTILES; tile += NBLK) {
        const size_t row0 = (size_t)tile * TR;

        // ---- initial A = p rows straight into C-fragment registers ----
        {
            const float* pA = p + (row0 + rwA) * 128 + colb;
            const float* pB = p + (row0 + rwB) * 128 + colb;
#pragma unroll
            for (int nt = 0; nt < 16; nt++) {
                float2 va = *(const float2*)(pA + nt * 8);
                float2 vb = *(const float2*)(pB + nt * 8);
                acc[nt][0] = va.x; acc[nt][1] = va.y;
                acc[nt][2] = vb.x; acc[nt][3] = vb.y;
            }
        }

        for (int g = 0; g < 12; g++) {
            // GEMM on current buffer contents (image g)
            pack_all(acc, aH, aL);
            gemm_step(acc, aH, aL, bbase);

            __syncthreads();   // all warps done reading buffer

            // start fetching next image; epilogue below hides the flight time
            {
                int gn = (g == 11) ? 0 : g + 1;
                copyB_async(sbase + SM_B0,
                            g_Bimg + (size_t)mat_for(gn) * IMG_ELEMS, tid);
            }

            if (g < 11) {
                epi_mid(g, acc, mus, rss, cb, cemb, cgam, cbet,
                        w, out, g_s_cta, row0, colb, rwA, rwB);
            } else {           // dw = -D
#pragma unroll
                for (int rb = 0; rb < 2; rb++) {
                    int rw = rb ? rwB : rwA;
                    float* dst = dwo + (row0 + rw) * 128 + colb;
#pragma unroll
                    for (int nt = 0; nt < 16; nt++)
                        *(float2*)(dst + nt * 8) =
                            make_float2(-acc[nt][2*rb], -acc[nt][2*rb+1]);
                }
            }

            asm volatile("cp.async.wait_group 0;" ::: "memory");
            __syncthreads();   // new image visible to all warps
        }
    }
}

// ---------------- launch ----------------
extern "C" void kernel_launch(void* const* d_in, const int* in_sizes, int n_in,
                              void* d_out, int out_size) {
    const float* t     = (const float*)d_in[0];
    const float* p     = (const float*)d_in[1];
    const float* w     = (const float*)d_in[2];
    const float* W_in  = (const float*)d_in[3];
    const float* b_in  = (const float*)d_in[4];
    const float* fw    = (const float*)d_in[5];
    const float* fb    = (const float*)d_in[6];
    const float* gamma = (const float*)d_in[7];
    const float* beta  = (const float*)d_in[8];
    const float* Wl    = (const float*)d_in[9];
    const float* bl    = (const float*)d_in[10];
    const float* W_out = (const float*)d_in[11];
    const float* b_out = (const float*)d_in[12];
    float* out = (float*)d_out;

    cudaFuncSetAttribute(clnf_main, cudaFuncAttributeMaxDynamicSharedMemorySize,
                         SM_TOTAL);

    int prep_total = 12 * 16384 + 512;
    prep_kernel<<<(prep_total + 255) / 256, 256>>>(t, W_in, fw, fb, Wl, W_out);
    clnf_main<<<NBLK, THREADS, SM_TOTAL>>>(p, w, b_in, gamma, beta, bl, b_out, out);
}